// round 11
// baseline (speedup 1.0000x reference)
#include <cuda_runtime.h>

// ---------------------------------------------------------------------------
// BoxCrossCategoryLoss, round 11: R9 math + 2-STAGE REGISTER PIPELINE.
// Diagnosis: DRAM duty-cycle 61% because each warp batches its 6 loads then
// computes ~500 cycles with nothing in flight. Fix: ping-pong prefetch so one
// element-set's loads are always outstanding while the other computes.
// No cur=next register copies (ping-pong stages, alternating guarded bodies).
// Math: log2-domain, fused NEG-recipe log1mexp, convex-max relu grouping,
// fused last-block reduction. rel_id inputs are dead.
// ---------------------------------------------------------------------------

#define GRID_BLOCKS 1480
#define NTHREADS 128

__device__ float        g_partials[GRID_BLOCKS];
__device__ unsigned int g_ctr = 0;

__device__ __forceinline__ float ex2f_(float x) {
    float r; asm("ex2.approx.f32 %0, %1;" : "=f"(r) : "f"(x)); return r;
}
__device__ __forceinline__ float lg2f_(float x) {
    float r; asm("lg2.approx.f32 %0, %1;" : "=f"(r) : "f"(x)); return r;
}

// sum of relu(S - xi) over a sorted triple, as max of chords
__device__ __forceinline__ float grp3(float S, float x1, float n12, float n123) {
    float t1 = S - x1;
    float t2 = __fmaf_rn(S, 2.0f, n12);
    float t3 = __fmaf_rn(S, 3.0f, n123);
    return fmaxf(fmaxf(t1, t2), fmaxf(t3, 0.0f));
}
__device__ __forceinline__ float grp2(float S, float x1, float n12) {
    float t1 = S - x1;
    float t2 = __fmaf_rn(S, 2.0f, n12);
    return fmaxf(fmaxf(t1, t2), 0.0f);
}

// One element; 12 inputs already scaled to log2 units.
__device__ __forceinline__ void elem_loss(
    float ab0, float ab1, float ba0, float ba1,
    float bc0, float bc1, float cb0, float cb1,
    float ac0, float ac1, float ca0, float ca1,
    float& q0, float& q1, float& q2, float& q3)
{
    float eab0 = ex2f_(ab0), eab1 = ex2f_(ab1);
    float eba0 = ex2f_(ba0), eba1 = ex2f_(ba1);
    float ebc0 = ex2f_(bc0), ebc1 = ex2f_(bc1);
    float ecb0 = ex2f_(cb0), ecb1 = ex2f_(cb1);
    float eac0 = ex2f_(ac0), eac1 = ex2f_(ac1);
    float eca0 = ex2f_(ca0), eca1 = ex2f_(ca1);

    float sab0 = 1.0f - eab0, sab1 = 1.0f - eab1;
    float sba0 = 1.0f - eba0, sba1 = 1.0f - eba1;
    float sbc0 = 1.0f - ebc0, sbc1 = 1.0f - ebc1;
    float scb0 = 1.0f - ecb0, scb1 = 1.0f - ecb1;
    float sac0 = 1.0f - eac0, sac1 = 1.0f - eac1;
    float sca0 = 1.0f - eca0, sca1 = 1.0f - eca1;

    float Lab0 = lg2f_(sab0), Lab1 = lg2f_(sab1);
    float Lba0 = lg2f_(sba0), Lba1 = lg2f_(sba1);
    float Lbc0 = lg2f_(sbc0), Lbc1 = lg2f_(sbc1);
    float Lcb0 = lg2f_(scb0), Lcb1 = lg2f_(scb1);
    float ACla1 = lg2f_(sac1), AClb1 = lg2f_(sca1);

    float w  = eac0 * eca0;
    float L0 = lg2f_(sac0 + w);
    float L1 = lg2f_(sca0 + w);
    float L2 = lg2f_(1.0f - w);

    float A0x = ab0 + Lba0, A1x = Lab0 + ba0, A2x = ab0 + ba0;
    float A0y = ab1 + Lba1, A1y = Lab1 + ba1, A2y = ab1 + ba1;
    float A3y = Lab1 + Lba1;
    float B0x = bc0 + Lcb0, B1x = Lbc0 + cb0, B2x = bc0 + cb0;
    float B0y = bc1 + Lcb1, B1y = Lbc1 + cb1, B2y = bc1 + cb1;
    float B3y = Lbc1 + Lcb1;
    float AC0 = ac1 + AClb1, AC1 = ACla1 + ca1;
    float AC2 = ac1 + ca1,   AC3 = ACla1 + AClb1;

    float g1lo = fminf(AC0, L1), g1hi = fmaxf(AC0, L1);
    float g1x3 = fmaxf(g1hi, L2), g1mid = fminf(g1hi, L2);
    float g1x1 = fminf(g1lo, g1mid), g1x2 = fmaxf(g1lo, g1mid);
    float g1n12  = (-g1x1) - g1x2;
    float g1n123 = g1n12 - g1x3;

    float g2lo = fminf(AC1, L0), g2hi = fmaxf(AC1, L0);
    float g2x3 = fmaxf(g2hi, L2), g2mid = fminf(g2hi, L2);
    float g2x1 = fminf(g2lo, g2mid), g2x2 = fmaxf(g2lo, g2mid);
    float g2n12  = (-g2x1) - g2x2;
    float g2n123 = g2n12 - g2x3;

    float g4x1 = fminf(AC3, L2);
    float g4n12 = (-AC3) - L2;

    q0 += grp3(A0x + B0y, g1x1, g1n12, g1n123);   // S1
    q1 += grp3(A0x + B2y, g1x1, g1n12, g1n123);   // S2
    q2 += grp3(A2x + B0y, g1x1, g1n12, g1n123);   // S5
    q3 += grp3(A0y + B0x, g1x1, g1n12, g1n123);   // S9
    q0 += grp3(A0y + B2x, g1x1, g1n12, g1n123);   // S10
    q1 += grp3(A1x + B1y, g2x1, g2n12, g2n123);   // S3
    q2 += grp3(A1x + B2y, g2x1, g2n12, g2n123);   // S4
    q3 += grp3(A2x + B1y, g2x1, g2n12, g2n123);   // S6
    q0 += grp3(A1y + B1x, g2x1, g2n12, g2n123);   // S11
    q1 += grp3(A1y + B2x, g2x1, g2n12, g2n123);   // S12
    q2 += fmaxf((A2x + B2y) - AC2, 0.0f);          // S7
    q3 += fmaxf((A2y + B2x) - AC2, 0.0f);          // S13
    q0 += grp2(A2x + B3y, g4x1, g4n12);            // S8
    q1 += grp2(A3y + B2x, g4x1, g4n12);            // S14
}

#define LOADSET(P, idx) \
    P##ab = AB4[idx]; P##ba = BA4[idx]; P##bc = BC4[idx]; \
    P##cb = CB4[idx]; P##ac = AC4[idx]; P##ca = CA4[idx];

#define COMPSET(P) \
    elem_loss(P##ab.x * K, P##ab.y * K, P##ba.x * K, P##ba.y * K, \
              P##bc.x * K, P##bc.y * K, P##cb.x * K, P##cb.y * K, \
              P##ac.x * K, P##ac.y * K, P##ca.x * K, P##ca.y * K, \
              q0, q1, q2, q3); \
    elem_loss(P##ab.z * K, P##ab.w * K, P##ba.z * K, P##ba.w * K, \
              P##bc.z * K, P##bc.w * K, P##cb.z * K, P##cb.w * K, \
              P##ac.z * K, P##ac.w * K, P##ca.z * K, P##ca.w * K, \
              q0, q1, q2, q3);

__global__ void __launch_bounds__(NTHREADS)
loss_kernel(const float* __restrict__ AB, const float* __restrict__ BA,
            const float* __restrict__ BC, const float* __restrict__ CB,
            const float* __restrict__ AC, const float* __restrict__ CA,
            int n_elems, float* __restrict__ out)
{
    constexpr float K = 1.44269504088896340736f;  // log2(e)
    const float4* AB4 = (const float4*)AB;
    const float4* BA4 = (const float4*)BA;
    const float4* BC4 = (const float4*)BC;
    const float4* CB4 = (const float4*)CB;
    const float4* AC4 = (const float4*)AC;
    const float4* CA4 = (const float4*)CA;

    const int stride = GRID_BLOCKS * NTHREADS;
    int n4 = n_elems >> 1;
    float q0 = 0.0f, q1 = 0.0f, q2 = 0.0f, q3 = 0.0f;

    float4 Pab, Pba, Pbc, Pcb, Pac, Pca;   // stage A
    float4 Qab, Qba, Qbc, Qcb, Qac, Qca;   // stage B

    int jA = blockIdx.x * NTHREADS + threadIdx.x;
    bool vA = jA < n4;
    if (vA) { LOADSET(P, jA) }

    #pragma unroll 1
    while (vA) {
        int jB = jA + stride;
        bool vB = jB < n4;
        if (vB) { LOADSET(Q, jB) }       // B loads in flight during compute A

        COMPSET(P)

        jA = jB + stride;
        vA = jA < n4;
        if (vA) { LOADSET(P, jA) }       // next-A loads in flight during compute B

        if (vB) { COMPSET(Q) }
    }

    // odd tail element (not hit for N = 8M)
    if ((n_elems & 1) && blockIdx.x == 0 && threadIdx.x == 0) {
        int i = n_elems - 1;
        elem_loss(AB[2*i] * K, AB[2*i+1] * K, BA[2*i] * K, BA[2*i+1] * K,
                  BC[2*i] * K, BC[2*i+1] * K, CB[2*i] * K, CB[2*i+1] * K,
                  AC[2*i] * K, AC[2*i+1] * K, CA[2*i] * K, CA[2*i+1] * K,
                  q0, q1, q2, q3);
    }

    float acc = (q0 + q1) + (q2 + q3);

    #pragma unroll
    for (int o = 16; o > 0; o >>= 1)
        acc += __shfl_xor_sync(0xFFFFFFFFu, acc, o);

    __shared__ float ws[NTHREADS / 32];
    __shared__ bool  amLast;
    if ((threadIdx.x & 31) == 0) ws[threadIdx.x >> 5] = acc;
    __syncthreads();
    if (threadIdx.x == 0) {
        float s = 0.0f;
        #pragma unroll
        for (int i = 0; i < NTHREADS / 32; i++) s += ws[i];
        g_partials[blockIdx.x] = s;
        __threadfence();
        unsigned old = atomicInc(&g_ctr, GRID_BLOCKS - 1);  // wraps to 0
        amLast = (old == GRID_BLOCKS - 1);
    }
    __syncthreads();

    if (amLast) {
        __shared__ double sh[NTHREADS];
        double s = 0.0;
        for (int i = threadIdx.x; i < GRID_BLOCKS; i += NTHREADS)
            s += (double)__ldcg(&g_partials[i]);
        sh[threadIdx.x] = s;
        __syncthreads();
        #pragma unroll
        for (int st = NTHREADS / 2; st > 0; st >>= 1) {
            if (threadIdx.x < st) sh[threadIdx.x] += sh[threadIdx.x + st];
            __syncthreads();
        }
        if (threadIdx.x == 0)
            out[0] = (float)(sh[0] * 0.69314718055994530942);  // log2 -> nat
    }
}

extern "C" void kernel_launch(void* const* d_in, const int* in_sizes, int n_in,
                              void* d_out, int out_size)
{
    const float* AB = (const float*)d_in[0];
    const float* BA = (const float*)d_in[1];
    const float* BC = (const float*)d_in[2];
    const float* CB = (const float*)d_in[3];
    const float* AC = (const float*)d_in[4];
    const float* CA = (const float*)d_in[5];
    // d_in[6..8] (xy/yz/xz rel_id) are dead inputs in the reference.

    int n_elems = in_sizes[0] / 2;

    loss_kernel<<<GRID_BLOCKS, NTHREADS>>>(AB, BA, BC, CB, AC, CA, n_elems,
                                           (float*)d_out);
}

// round 12
// speedup vs baseline: 1.0076x; 1.0076x over previous
#include <cuda_runtime.h>
#include <cstdint>

// ---------------------------------------------------------------------------
// BoxCrossCategoryLoss, round 12: cp.async.bulk staged pipeline.
// All rounds were DRAM-limited at ~4.7-5.0 TB/s (wall == 384MB/BW exactly).
// Hypothesis: ~7000 concurrent 4KB LDG windows thrash DRAM rows. Fix: 148
// CTAs x 512 thr, 4-stage smem pipeline, 6 x 8KB cp.async.bulk per stage ->
// 888 windows, 8KB sequential bursts. Compute = R9 math from smem.
// ---------------------------------------------------------------------------

#define GRID_ 148
#define CTAT 512
#define NSTAGES 4
#define CHUNK_F4 512                       // float4s per array per stage
#define CHUNK_BYTES (CHUNK_F4 * 16)        // 8192
#define STAGE_BYTES (6 * CHUNK_BYTES)      // 49152
#define SMEM_TOTAL (NSTAGES * STAGE_BYTES) // 196608

__device__ float        g_partials[GRID_];
__device__ unsigned int g_ctr = 0;

__device__ __forceinline__ float ex2f_(float x) {
    float r; asm("ex2.approx.f32 %0, %1;" : "=f"(r) : "f"(x)); return r;
}
__device__ __forceinline__ float lg2f_(float x) {
    float r; asm("lg2.approx.f32 %0, %1;" : "=f"(r) : "f"(x)); return r;
}
__device__ __forceinline__ uint32_t s2u32(const void* p) {
    uint32_t a;
    asm("{ .reg .u64 t; cvta.to.shared.u64 t, %1; cvt.u32.u64 %0, t; }"
        : "=r"(a) : "l"(p));
    return a;
}
__device__ __forceinline__ void mbar_init(uint32_t m, uint32_t cnt) {
    asm volatile("mbarrier.init.shared.b64 [%0], %1;" :: "r"(m), "r"(cnt) : "memory");
}
__device__ __forceinline__ void mbar_inval(uint32_t m) {
    asm volatile("mbarrier.inval.shared.b64 [%0];" :: "r"(m) : "memory");
}
__device__ __forceinline__ void mbar_arrive(uint32_t m) {
    asm volatile("mbarrier.arrive.shared.b64 _, [%0];" :: "r"(m) : "memory");
}
__device__ __forceinline__ void mbar_expect_tx(uint32_t m, uint32_t bytes) {
    asm volatile("mbarrier.arrive.expect_tx.shared.b64 _, [%0], %1;"
                 :: "r"(m), "r"(bytes) : "memory");
}
__device__ __forceinline__ void mbar_wait(uint32_t m, uint32_t parity) {
    asm volatile(
        "{\n\t.reg .pred P;\n\t"
        "W_%=:\n\t"
        "mbarrier.try_wait.parity.acquire.cta.shared::cta.b64 P, [%0], %1, 0x989680;\n\t"
        "@P bra W_DONE_%=;\n\t"
        "bra W_%=;\n\t"
        "W_DONE_%=:\n\t}"
        :: "r"(m), "r"(parity) : "memory");
}
__device__ __forceinline__ void bulk_ld(uint32_t dst, const void* src,
                                        uint32_t bytes, uint32_t mbar) {
    asm volatile(
        "cp.async.bulk.shared::cluster.global.mbarrier::complete_tx::bytes "
        "[%0], [%1], %2, [%3];"
        :: "r"(dst), "l"(src), "r"(bytes), "r"(mbar) : "memory");
}

// sum of relu(S - xi) over a sorted triple, as max of chords
__device__ __forceinline__ float grp3(float S, float x1, float n12, float n123) {
    float t1 = S - x1;
    float t2 = __fmaf_rn(S, 2.0f, n12);
    float t3 = __fmaf_rn(S, 3.0f, n123);
    return fmaxf(fmaxf(t1, t2), fmaxf(t3, 0.0f));
}
__device__ __forceinline__ float grp2(float S, float x1, float n12) {
    float t1 = S - x1;
    float t2 = __fmaf_rn(S, 2.0f, n12);
    return fmaxf(fmaxf(t1, t2), 0.0f);
}

__device__ __forceinline__ void elem_loss(
    float ab0, float ab1, float ba0, float ba1,
    float bc0, float bc1, float cb0, float cb1,
    float ac0, float ac1, float ca0, float ca1,
    float& q0, float& q1, float& q2, float& q3)
{
    float eab0 = ex2f_(ab0), eab1 = ex2f_(ab1);
    float eba0 = ex2f_(ba0), eba1 = ex2f_(ba1);
    float ebc0 = ex2f_(bc0), ebc1 = ex2f_(bc1);
    float ecb0 = ex2f_(cb0), ecb1 = ex2f_(cb1);
    float eac0 = ex2f_(ac0), eac1 = ex2f_(ac1);
    float eca0 = ex2f_(ca0), eca1 = ex2f_(ca1);

    float sab0 = 1.0f - eab0, sab1 = 1.0f - eab1;
    float sba0 = 1.0f - eba0, sba1 = 1.0f - eba1;
    float sbc0 = 1.0f - ebc0, sbc1 = 1.0f - ebc1;
    float scb0 = 1.0f - ecb0, scb1 = 1.0f - ecb1;
    float sac1 = 1.0f - eac1, sca1 = 1.0f - eca1;
    float sac0 = 1.0f - eac0, sca0 = 1.0f - eca0;

    float Lab0 = lg2f_(sab0), Lab1 = lg2f_(sab1);
    float Lba0 = lg2f_(sba0), Lba1 = lg2f_(sba1);
    float Lbc0 = lg2f_(sbc0), Lbc1 = lg2f_(sbc1);
    float Lcb0 = lg2f_(scb0), Lcb1 = lg2f_(scb1);
    float ACla1 = lg2f_(sac1), AClb1 = lg2f_(sca1);

    float w  = eac0 * eca0;
    float L0 = lg2f_(sac0 + w);
    float L1 = lg2f_(sca0 + w);
    float L2 = lg2f_(1.0f - w);

    float A0x = ab0 + Lba0, A1x = Lab0 + ba0, A2x = ab0 + ba0;
    float A0y = ab1 + Lba1, A1y = Lab1 + ba1, A2y = ab1 + ba1;
    float A3y = Lab1 + Lba1;
    float B0x = bc0 + Lcb0, B1x = Lbc0 + cb0, B2x = bc0 + cb0;
    float B0y = bc1 + Lcb1, B1y = Lbc1 + cb1, B2y = bc1 + cb1;
    float B3y = Lbc1 + Lcb1;
    float AC0 = ac1 + AClb1, AC1 = ACla1 + ca1;
    float AC2 = ac1 + ca1,   AC3 = ACla1 + AClb1;

    float g1lo = fminf(AC0, L1), g1hi = fmaxf(AC0, L1);
    float g1x3 = fmaxf(g1hi, L2), g1mid = fminf(g1hi, L2);
    float g1x1 = fminf(g1lo, g1mid), g1x2 = fmaxf(g1lo, g1mid);
    float g1n12  = (-g1x1) - g1x2;
    float g1n123 = g1n12 - g1x3;

    float g2lo = fminf(AC1, L0), g2hi = fmaxf(AC1, L0);
    float g2x3 = fmaxf(g2hi, L2), g2mid = fminf(g2hi, L2);
    float g2x1 = fminf(g2lo, g2mid), g2x2 = fmaxf(g2lo, g2mid);
    float g2n12  = (-g2x1) - g2x2;
    float g2n123 = g2n12 - g2x3;

    float g4x1 = fminf(AC3, L2);
    float g4n12 = (-AC3) - L2;

    q0 += grp3(A0x + B0y, g1x1, g1n12, g1n123);   // S1
    q1 += grp3(A0x + B2y, g1x1, g1n12, g1n123);   // S2
    q2 += grp3(A2x + B0y, g1x1, g1n12, g1n123);   // S5
    q3 += grp3(A0y + B0x, g1x1, g1n12, g1n123);   // S9
    q0 += grp3(A0y + B2x, g1x1, g1n12, g1n123);   // S10
    q1 += grp3(A1x + B1y, g2x1, g2n12, g2n123);   // S3
    q2 += grp3(A1x + B2y, g2x1, g2n12, g2n123);   // S4
    q3 += grp3(A2x + B1y, g2x1, g2n12, g2n123);   // S6
    q0 += grp3(A1y + B1x, g2x1, g2n12, g2n123);   // S11
    q1 += grp3(A1y + B2x, g2x1, g2n12, g2n123);   // S12
    q2 += fmaxf((A2x + B2y) - AC2, 0.0f);          // S7
    q3 += fmaxf((A2y + B2x) - AC2, 0.0f);          // S13
    q0 += grp2(A2x + B3y, g4x1, g4n12);            // S8
    q1 += grp2(A3y + B2x, g4x1, g4n12);            // S14
}

extern __shared__ float4 dsm[];   // [NSTAGES][6][CHUNK_F4]

__global__ void __launch_bounds__(CTAT)
loss_kernel(const float* __restrict__ AB, const float* __restrict__ BA,
            const float* __restrict__ BC, const float* __restrict__ CB,
            const float* __restrict__ AC, const float* __restrict__ CA,
            int n_elems, float* __restrict__ out)
{
    constexpr float K = 1.44269504088896340736f;  // log2(e)
    const int tid = threadIdx.x;
    const int bx  = blockIdx.x;

    __shared__ __align__(8) uint64_t mbar_sto[2 * NSTAGES];  // full[4], empty[4]
    uint32_t full0  = s2u32(&mbar_sto[0]);
    uint32_t empty0 = s2u32(&mbar_sto[NSTAGES]);
    uint32_t smem0  = s2u32(dsm);

    if (tid == 0) {
        #pragma unroll
        for (int s = 0; s < NSTAGES; s++) {
            mbar_init(full0  + 8u * s, 1);
            mbar_init(empty0 + 8u * s, CTAT);
        }
        asm volatile("fence.proxy.async.shared::cta;" ::: "memory");
    }
    __syncthreads();

    const float* srcs[6] = { AB, BA, BC, CB, AC, CA };

    int n4 = n_elems >> 1;          // float4 count per array
    int NC = n4 / CHUNK_F4;         // full chunks (8192 for N=8M)

    // prologue: fill up to NSTAGES stages
    if (tid == 0) {
        #pragma unroll
        for (int p = 0; p < NSTAGES; p++) {
            int g = bx + p * GRID_;
            if (g < NC) {
                uint32_t fb = full0 + 8u * p;
                mbar_expect_tx(fb, STAGE_BYTES);
                uint32_t dst = smem0 + (uint32_t)p * STAGE_BYTES;
                long off = (long)g * CHUNK_F4 * 4;   // float offset
                #pragma unroll
                for (int a = 0; a < 6; a++)
                    bulk_ld(dst + a * CHUNK_BYTES, srcs[a] + off, CHUNK_BYTES, fb);
            }
        }
    }

    float q0 = 0.0f, q1 = 0.0f, q2 = 0.0f, q3 = 0.0f;

    int k = 0;
    for (int g = bx; g < NC; g += GRID_, ++k) {
        int s = k & (NSTAGES - 1);
        uint32_t ph = (k >> 2) & 1;
        uint32_t fb = full0 + 8u * s;
        uint32_t eb = empty0 + 8u * s;

        mbar_wait(fb, ph);

        const float4* st = dsm + (size_t)s * 6 * CHUNK_F4;
        float4 vab = st[0 * CHUNK_F4 + tid];
        float4 vba = st[1 * CHUNK_F4 + tid];
        float4 vbc = st[2 * CHUNK_F4 + tid];
        float4 vcb = st[3 * CHUNK_F4 + tid];
        float4 vac = st[4 * CHUNK_F4 + tid];
        float4 vca = st[5 * CHUNK_F4 + tid];

        mbar_arrive(eb);

        // refill this stage for chunk g + 4*GRID_ (producer thread only)
        if (tid == 0) {
            int gn = g + NSTAGES * GRID_;
            if (gn < NC) {
                mbar_wait(eb, ph);               // all 512 consumed
                mbar_expect_tx(fb, STAGE_BYTES);
                uint32_t dst = smem0 + (uint32_t)s * STAGE_BYTES;
                long off = (long)gn * CHUNK_F4 * 4;
                #pragma unroll
                for (int a = 0; a < 6; a++)
                    bulk_ld(dst + a * CHUNK_BYTES, srcs[a] + off, CHUNK_BYTES, fb);
            }
        }

        elem_loss(vab.x * K, vab.y * K, vba.x * K, vba.y * K,
                  vbc.x * K, vbc.y * K, vcb.x * K, vcb.y * K,
                  vac.x * K, vac.y * K, vca.x * K, vca.y * K,
                  q0, q1, q2, q3);
        elem_loss(vab.z * K, vab.w * K, vba.z * K, vba.w * K,
                  vbc.z * K, vbc.w * K, vcb.z * K, vcb.w * K,
                  vac.z * K, vac.w * K, vca.z * K, vca.w * K,
                  q0, q1, q2, q3);
    }

    // leftover float4s beyond NC*CHUNK_F4 (zero for N=8M) + odd element
    if (bx == 0) {
        for (int j = NC * CHUNK_F4 + tid; j < n4; j += CTAT) {
            const float4* AB4 = (const float4*)AB;
            const float4* BA4 = (const float4*)BA;
            const float4* BC4 = (const float4*)BC;
            const float4* CB4 = (const float4*)CB;
            const float4* AC4 = (const float4*)AC;
            const float4* CA4 = (const float4*)CA;
            float4 vab = AB4[j], vba = BA4[j], vbc = BC4[j];
            float4 vcb = CB4[j], vac = AC4[j], vca = CA4[j];
            elem_loss(vab.x * K, vab.y * K, vba.x * K, vba.y * K,
                      vbc.x * K, vbc.y * K, vcb.x * K, vcb.y * K,
                      vac.x * K, vac.y * K, vca.x * K, vca.y * K,
                      q0, q1, q2, q3);
            elem_loss(vab.z * K, vab.w * K, vba.z * K, vba.w * K,
                      vbc.z * K, vbc.w * K, vcb.z * K, vcb.w * K,
                      vac.z * K, vac.w * K, vca.z * K, vca.w * K,
                      q0, q1, q2, q3);
        }
        if ((n_elems & 1) && tid == 0) {
            int i = n_elems - 1;
            elem_loss(AB[2*i] * K, AB[2*i+1] * K, BA[2*i] * K, BA[2*i+1] * K,
                      BC[2*i] * K, BC[2*i+1] * K, CB[2*i] * K, CB[2*i+1] * K,
                      AC[2*i] * K, AC[2*i+1] * K, CA[2*i] * K, CA[2*i+1] * K,
                      q0, q1, q2, q3);
        }
    }

    float acc = (q0 + q1) + (q2 + q3);

    #pragma unroll
    for (int o = 16; o > 0; o >>= 1)
        acc += __shfl_xor_sync(0xFFFFFFFFu, acc, o);

    __shared__ float ws[CTAT / 32];
    __shared__ bool  amLast;
    if ((tid & 31) == 0) ws[tid >> 5] = acc;
    __syncthreads();
    if (tid == 0) {
        float sum = 0.0f;
        #pragma unroll
        for (int i = 0; i < CTAT / 32; i++) sum += ws[i];
        g_partials[bx] = sum;
        __threadfence();
        unsigned old = atomicInc(&g_ctr, GRID_ - 1);   // wraps to 0
        amLast = (old == GRID_ - 1);
        // clean up barriers for next (re)launch
        #pragma unroll
        for (int s = 0; s < NSTAGES; s++) {
            mbar_inval(full0 + 8u * s);
            mbar_inval(empty0 + 8u * s);
        }
    }
    __syncthreads();

    if (amLast) {
        float s = (tid < GRID_) ? __ldcg(&g_partials[tid]) : 0.0f;
        __shared__ double sh[CTAT];
        sh[tid] = (double)s;
        __syncthreads();
        #pragma unroll
        for (int st = CTAT / 2; st > 0; st >>= 1) {
            if (tid < st) sh[tid] += sh[tid + st];
            __syncthreads();
        }
        if (tid == 0)
            out[0] = (float)(sh[0] * 0.69314718055994530942);  // log2 -> nat
    }
}

extern "C" void kernel_launch(void* const* d_in, const int* in_sizes, int n_in,
                              void* d_out, int out_size)
{
    const float* AB = (const float*)d_in[0];
    const float* BA = (const float*)d_in[1];
    const float* BC = (const float*)d_in[2];
    const float* CB = (const float*)d_in[3];
    const float* AC = (const float*)d_in[4];
    const float* CA = (const float*)d_in[5];
    // d_in[6..8] (xy/yz/xz rel_id) are dead inputs in the reference.

    int n_elems = in_sizes[0] / 2;

    static bool attr_done = false;   // idempotent attribute set (not a guard on work)
    if (!attr_done) {
        cudaFuncSetAttribute(loss_kernel,
                             cudaFuncAttributeMaxDynamicSharedMemorySize,
                             SMEM_TOTAL);
        attr_done = true;
    }

    loss_kernel<<<GRID_, CTAT, SMEM_TOTAL>>>(AB, BA, BC, CB, AC, CA, n_elems,
                                             (float*)d_out);
}

// round 13
// speedup vs baseline: 1.0682x; 1.0602x over previous
#include <cuda_runtime.h>

// ---------------------------------------------------------------------------
// BoxCrossCategoryLoss, round 13: recombination of the two best measured
// components. (1) R2's plain scalar elem_loss + grid-stride loop VERBATIM —
// the only body that achieved 5.42 TB/s / ~71us main. (2) fused last-block
// reduction — measured ~free in R5 (main 77.5 vs total 77.9), removes the
// ~7us separate reduce launch R2 paid.
// log2-domain math, fused NEG-recipe log1mexp. rel_id inputs are dead.
// ---------------------------------------------------------------------------

#define GRID_BLOCKS 1216
#define NTHREADS 256

__device__ float        g_partials[GRID_BLOCKS];
__device__ unsigned int g_ctr = 0;

__device__ __forceinline__ float ex2f_(float x) {
    float r; asm("ex2.approx.f32 %0, %1;" : "=f"(r) : "f"(x)); return r;
}
__device__ __forceinline__ float lg2f_(float x) {
    float r; asm("lg2.approx.f32 %0, %1;" : "=f"(r) : "f"(x)); return r;
}
// log2(1 - 2^x)  for x < 0 (x in log2 units)
__device__ __forceinline__ float l1m2(float x) {
    return lg2f_(1.0f - ex2f_(x));
}

// Per-element loss in log2 units. All 12 inputs are natural-log values
// pre-scaled by log2(e).   [R2 body, verbatim]
__device__ __forceinline__ float elem_loss(
    float ab0, float ab1, float ba0, float ba1,
    float bc0, float bc1, float cb0, float cb1,
    float ac0, float ac1, float ca0, float ca1)
{
    // --- AB pair (v1 = vol_AB, v2 = vol_BA) ---
    float ABla0 = l1m2(ab0), ABlb0 = l1m2(ba0);
    float ABla1 = l1m2(ab1), ABlb1 = l1m2(ba1);
    float AB0c0 = ab0 + ABlb0;              // PC col0
    float AB1c0 = ABla0 + ba0;              // CP col0
    float AB2c0 = ab0 + ba0;                // CR col0
    float AB0c1 = ab1 + ABlb1;
    float AB1c1 = ABla1 + ba1;
    float AB2c1 = ab1 + ba1;
    float AB3c1 = ABla1 + ABlb1;            // NR col1

    // --- BC pair ---
    float BCla0 = l1m2(bc0), BClb0 = l1m2(cb0);
    float BCla1 = l1m2(bc1), BClb1 = l1m2(cb1);
    float BC0c0 = bc0 + BClb0;
    float BC1c0 = BCla0 + cb0;
    float BC2c0 = bc0 + cb0;
    float BC0c1 = bc1 + BClb1;
    float BC1c1 = BCla1 + cb1;
    float BC2c1 = bc1 + cb1;
    float BC3c1 = BCla1 + BClb1;

    // --- AC pair, column 1 (used directly in LOSS_RECIPE) ---
    float ACla1 = l1m2(ac1), AClb1 = l1m2(ca1);
    float AC0 = ac1 + AClb1;
    float AC1 = ACla1 + ca1;
    float AC2 = ac1 + ca1;
    float AC3 = ACla1 + AClb1;

    // --- AC pair, column 0: only log1mexp(pAC[k][:,0]) is ever needed ---
    float ua = ex2f_(ac0);
    float ub = ex2f_(ca0);
    float w  = ua * ub;
    float L0 = lg2f_((1.0f - ua) + w);            // log2(1 - ua(1-ub))
    float L1 = lg2f_((1.0f - ub) + w);            // log2(1 - (1-ua)ub)
    float L2 = lg2f_(__fmaf_rn(-ua, ub, 1.0f));   // log2(1 - ua*ub)

    float acc = 0.0f;
#define RTERM(S, X) acc += fmaxf((S) - (X), 0.0f);

    float S1  = AB0c0 + BC0c1;  RTERM(S1,  AC0) RTERM(S1,  L1) RTERM(S1,  L2)
    float S2  = AB0c0 + BC2c1;  RTERM(S2,  AC0) RTERM(S2,  L1) RTERM(S2,  L2)
    float S3  = AB1c0 + BC1c1;  RTERM(S3,  AC1) RTERM(S3,  L0) RTERM(S3,  L2)
    float S4  = AB1c0 + BC2c1;  RTERM(S4,  AC1) RTERM(S4,  L0) RTERM(S4,  L2)
    float S5  = AB2c0 + BC0c1;  RTERM(S5,  AC0) RTERM(S5,  L1) RTERM(S5,  L2)
    float S6  = AB2c0 + BC1c1;  RTERM(S6,  AC1) RTERM(S6,  L0) RTERM(S6,  L2)
    float S7  = AB2c0 + BC2c1;  RTERM(S7,  AC2)
    float S8  = AB2c0 + BC3c1;  RTERM(S8,  AC3) RTERM(S8,  L2)
    float S9  = AB0c1 + BC0c0;  RTERM(S9,  AC0) RTERM(S9,  L1) RTERM(S9,  L2)
    float S10 = AB0c1 + BC2c0;  RTERM(S10, AC0) RTERM(S10, L1) RTERM(S10, L2)
    float S11 = AB1c1 + BC1c0;  RTERM(S11, AC1) RTERM(S11, L0) RTERM(S11, L2)
    float S12 = AB1c1 + BC2c0;  RTERM(S12, AC1) RTERM(S12, L0) RTERM(S12, L2)
    float S13 = AB2c1 + BC2c0;  RTERM(S13, AC2)
    float S14 = AB3c1 + BC2c0;  RTERM(S14, AC3) RTERM(S14, L2)
#undef RTERM
    return acc;
}

__global__ void __launch_bounds__(NTHREADS)
loss_kernel(const float* __restrict__ AB, const float* __restrict__ BA,
            const float* __restrict__ BC, const float* __restrict__ CB,
            const float* __restrict__ AC, const float* __restrict__ CA,
            int n_elems, float* __restrict__ out)
{
    constexpr float K = 1.44269504088896340736f;  // log2(e)
    const float4* AB4 = (const float4*)AB;
    const float4* BA4 = (const float4*)BA;
    const float4* BC4 = (const float4*)BC;
    const float4* CB4 = (const float4*)CB;
    const float4* AC4 = (const float4*)AC;
    const float4* CA4 = (const float4*)CA;

    int n4 = n_elems >> 1;  // each float4 covers 2 elements (2 cols each)
    float acc = 0.0f;

    for (int j = blockIdx.x * NTHREADS + threadIdx.x; j < n4;
         j += GRID_BLOCKS * NTHREADS) {
        float4 vab = AB4[j], vba = BA4[j];
        float4 vbc = BC4[j], vcb = CB4[j];
        float4 vac = AC4[j], vca = CA4[j];

        acc += elem_loss(vab.x * K, vab.y * K, vba.x * K, vba.y * K,
                         vbc.x * K, vbc.y * K, vcb.x * K, vcb.y * K,
                         vac.x * K, vac.y * K, vca.x * K, vca.y * K);
        acc += elem_loss(vab.z * K, vab.w * K, vba.z * K, vba.w * K,
                         vbc.z * K, vbc.w * K, vcb.z * K, vcb.w * K,
                         vac.z * K, vac.w * K, vca.z * K, vca.w * K);
    }

    // odd tail element (not hit for N = 8M, kept for generality)
    if ((n_elems & 1) && blockIdx.x == 0 && threadIdx.x == 0) {
        int i = n_elems - 1;
        acc += elem_loss(AB[2*i] * K, AB[2*i+1] * K, BA[2*i] * K, BA[2*i+1] * K,
                         BC[2*i] * K, BC[2*i+1] * K, CB[2*i] * K, CB[2*i+1] * K,
                         AC[2*i] * K, AC[2*i+1] * K, CA[2*i] * K, CA[2*i+1] * K);
    }

    // warp + block reduction (fixed order -> deterministic)
    #pragma unroll
    for (int o = 16; o > 0; o >>= 1)
        acc += __shfl_xor_sync(0xFFFFFFFFu, acc, o);

    __shared__ float ws[NTHREADS / 32];
    __shared__ bool  amLast;
    if ((threadIdx.x & 31) == 0) ws[threadIdx.x >> 5] = acc;
    __syncthreads();
    if (threadIdx.x == 0) {
        float s = 0.0f;
        #pragma unroll
        for (int i = 0; i < NTHREADS / 32; i++) s += ws[i];
        g_partials[blockIdx.x] = s;
        __threadfence();
        unsigned old = atomicInc(&g_ctr, GRID_BLOCKS - 1);  // wraps to 0
        amLast = (old == GRID_BLOCKS - 1);
    }
    __syncthreads();

    if (amLast) {
        __shared__ double sh[NTHREADS];
        double s = 0.0;
        for (int i = threadIdx.x; i < GRID_BLOCKS; i += NTHREADS)
            s += (double)__ldcg(&g_partials[i]);
        sh[threadIdx.x] = s;
        __syncthreads();
        #pragma unroll
        for (int st = NTHREADS / 2; st > 0; st >>= 1) {
            if (threadIdx.x < st) sh[threadIdx.x] += sh[threadIdx.x + st];
            __syncthreads();
        }
        if (threadIdx.x == 0)
            out[0] = (float)(sh[0] * 0.69314718055994530942);  // log2 -> nat
    }
}

extern "C" void kernel_launch(void* const* d_in, const int* in_sizes, int n_in,
                              void* d_out, int out_size)
{
    const float* AB = (const float*)d_in[0];
    const float* BA = (const float*)d_in[1];
    const float* BC = (const float*)d_in[2];
    const float* CB = (const float*)d_in[3];
    const float* AC = (const float*)d_in[4];
    const float* CA = (const float*)d_in[5];
    // d_in[6..8] (xy/yz/xz rel_id) are dead inputs in the reference.

    int n_elems = in_sizes[0] / 2;

    loss_kernel<<<GRID_BLOCKS, NTHREADS>>>(AB, BA, BC, CB, AC, CA, n_elems,
                                           (float*)d_out);
}